// round 13
// baseline (speedup 1.0000x reference)
#include <cuda_runtime.h>
#include <cuda_fp16.h>
#include <cstdint>
#include <type_traits>

// ---------------- problem constants ----------------
#define B_      16
#define Q_      300
#define DMODEL  256
#define NHEADS  8
#define HD      32
#define LV      8400          // 80*80 + 40*40 + 20*20
#define BQ      (B_*Q_)       // 4800
#define MV      (B_*LV)       // 134400 value rows
#define MT_PAD  4864          // 38*128

// ---------------- scratch (device globals; zero-initialized) ----------------
__device__ __half g_val16[MV * DMODEL];               // raw value, fp16
__device__ __half g_qv16[NHEADS * MT_PAD * DMODEL];   // reduced sample vecs [h][bq][256]
__device__ __half g_tmp16[MT_PAD * DMODEL];           // projected heads; pad rows stay 0
__device__ __half g_wo16[DMODEL * DMODEL];            // Wout fp16
__device__ float  g_off[BQ * 192];
__device__ float  g_attn[BQ * 96];

// ---------------- helpers ----------------
__device__ __forceinline__ uint32_t smem_u32(const void* p) {
    uint32_t a;
    asm("{ .reg .u64 t; cvta.to.shared.u64 t, %1; cvt.u32.u64 %0, t; }" : "=r"(a) : "l"(p));
    return a;
}
__device__ __forceinline__ void ldsm_x4(uint32_t* r, uint32_t addr) {
    asm volatile("ldmatrix.sync.aligned.m8n8.x4.shared.b16 {%0,%1,%2,%3}, [%4];"
                 : "=r"(r[0]), "=r"(r[1]), "=r"(r[2]), "=r"(r[3]) : "r"(addr));
}
__device__ __forceinline__ void ldsm_x4_t(uint32_t* r, uint32_t addr) {
    asm volatile("ldmatrix.sync.aligned.m8n8.x4.trans.shared.b16 {%0,%1,%2,%3}, [%4];"
                 : "=r"(r[0]), "=r"(r[1]), "=r"(r[2]), "=r"(r[3]) : "r"(addr));
}
__device__ __forceinline__ void mma16(float* c, const uint32_t* a, const uint32_t* b) {
    asm volatile(
        "mma.sync.aligned.m16n8k16.row.col.f32.f16.f16.f32 "
        "{%0,%1,%2,%3}, {%4,%5,%6,%7}, {%8,%9}, {%0,%1,%2,%3};\n"
        : "+f"(c[0]), "+f"(c[1]), "+f"(c[2]), "+f"(c[3])
        : "r"(a[0]), "r"(a[1]), "r"(a[2]), "r"(a[3]), "r"(b[0]), "r"(b[1]));
}
__device__ __forceinline__ uint32_t packh2(float x, float y) {
    __half2 h = __floats2half2_rn(x, y);
    return *reinterpret_cast<uint32_t*>(&h);
}

// ---------------- geometry ----------------
#define BK       32
#define ASTR     40
#define A_HALVES (128 * ASTR)
#define STAGE_H  (A_HALVES + 32 * 72)
#define SMEM_G2  (3 * STAGE_H * 2)         // 44544 B

// proj smem: A 64x264 halves + W 256x40 halves
#define PJ_ASTR  264
#define PJ_WSTR  40
#define SMEM_PJ  ((64 * PJ_ASTR + 256 * PJ_WSTR) * 2)   // 54272 B

#define NVAL (MV * DMODEL)                 // 34,406,400
#define NTOT (NVAL + DMODEL * DMODEL)      // 34,471,936

// ============================================================================
// fp32 -> fp16: value + Wout in one launch
// ============================================================================
__global__ void cvt_all(const float* __restrict__ val, __half* __restrict__ dval,
                        const float* __restrict__ wo, __half* __restrict__ dwo) {
    long i = ((long)blockIdx.x * blockDim.x + threadIdx.x) * 4;
    if (i >= NTOT) return;
    const float* s; __half* d; long j;
    if (i < NVAL) { s = val; d = dval; j = i; }
    else          { s = wo;  d = dwo;  j = i - NVAL; }
    float4 v = *reinterpret_cast<const float4*>(s + j);
    uint2 u = make_uint2(packh2(v.x, v.y), packh2(v.z, v.w));
    *reinterpret_cast<uint2*>(d + j) = u;
}

// ============================================================================
// Fused exact fp32 GEMM for offsets + attn logits. Tile 32x32, BK=64.
// grid (9, 150). bx 0..5 -> Woff/g_off, 6..8 -> Wattn/g_attn.
// ============================================================================
__global__ __launch_bounds__(256, 6)
void fgemm_qfused(const float* __restrict__ A,
                  const float* __restrict__ Woff, const float* __restrict__ boff,
                  const float* __restrict__ Wattn, const float* __restrict__ battn,
                  float* __restrict__ Coff, float* __restrict__ Cattn) {
    __shared__ float As[32 * 68];
    __shared__ float Bs[64 * 36];
    const int tid = threadIdx.x;
    const int bx = blockIdx.x;
    const int m0 = blockIdx.y * 32;

    const float* Bm; const float* bias; float* C; int N; int n0;
    if (bx < 6) { Bm = Woff;  bias = boff;  C = Coff;  N = 192; n0 = bx * 32; }
    else        { Bm = Wattn; bias = battn; C = Cattn; N = 96;  n0 = (bx - 6) * 32; }

    const int ty = tid >> 4, tx = tid & 15;
    const int arow = tid >> 3, acol = (tid & 7) * 4;

    float acc[2][2] = {};
    for (int kc = 0; kc < 256; kc += 64) {
        #pragma unroll
        for (int i = 0; i < 2; i++)
            *reinterpret_cast<float4*>(&As[arow * 68 + acol + 32 * i]) =
                *reinterpret_cast<const float4*>(A + (size_t)(m0 + arow) * 256 + kc + acol + 32 * i);
        #pragma unroll
        for (int i = 0; i < 2; i++)
            *reinterpret_cast<float4*>(&Bs[(arow + 32 * i) * 36 + acol]) =
                *reinterpret_cast<const float4*>(Bm + (size_t)(kc + arow + 32 * i) * N + n0 + acol);
        __syncthreads();
        #pragma unroll
        for (int kk = 0; kk < 64; kk++) {
            const float a0 = As[(ty * 2 + 0) * 68 + kk];
            const float a1 = As[(ty * 2 + 1) * 68 + kk];
            const float2 bv = *reinterpret_cast<const float2*>(&Bs[kk * 36 + tx * 2]);
            acc[0][0] += a0 * bv.x;  acc[0][1] += a0 * bv.y;
            acc[1][0] += a1 * bv.x;  acc[1][1] += a1 * bv.y;
        }
        __syncthreads();
    }
    const float b0 = bias[n0 + tx * 2], b1 = bias[n0 + tx * 2 + 1];
    #pragma unroll
    for (int i = 0; i < 2; i++) {
        float2 v = make_float2(acc[i][0] + b0, acc[i][1] + b1);
        *reinterpret_cast<float2*>(&C[(size_t)(m0 + ty * 2 + i) * N + n0 + tx * 2]) = v;
    }
}

// ============================================================================
// sample_reduce: one warp per (bq, h). Lanes 0-11 own a (level,point):
// softmax + clamped corner indices + validity-folded weights. All 32 lanes
// gather RAW 256-dim fp16 value rows (8 dims/lane) and weighted-accumulate
// over 12 points x 4 corners -> g_qv16[h][bq][256].
// ============================================================================
__global__ __launch_bounds__(256)
void sample_reduce(const float* __restrict__ off, const float* __restrict__ attn,
                   const float* __restrict__ rp, const __half* __restrict__ val,
                   __half* __restrict__ qv) {
    const int bq   = blockIdx.x;
    const int h    = threadIdx.x >> 5;
    const int lane = threadIdx.x & 31;
    const int b    = bq / Q_;

    const float refx = rp[bq * 4 + 0];
    const float refy = rp[bq * 4 + 1];

    float logit = -1e30f, px = 0.f, py = 0.f;
    int W = 1, start = 0;
    if (lane < 12) {
        logit = attn[bq * 96 + h * 12 + lane];
        const float ox = off[bq * 192 + h * 24 + lane * 2 + 0];
        const float oy = off[bq * 192 + h * 24 + lane * 2 + 1];
        const int lvl = lane >> 2;
        W     = (lvl == 0) ? 80 : ((lvl == 1) ? 40 : 20);
        start = (lvl == 0) ? 0 : ((lvl == 1) ? 6400 : 8000);
        const float Wf = (float)W;
        const float ptsx = fminf(fmaxf(refx + ox, 0.f), 1.f);
        const float ptsy = fminf(fmaxf(refy + oy, 0.f), 1.f);
        px = ptsx * Wf - 0.5f;
        py = ptsy * Wf - 0.5f;
    }
    float mx = logit;
    #pragma unroll
    for (int s = 16; s > 0; s >>= 1) mx = fmaxf(mx, __shfl_xor_sync(0xffffffffu, mx, s));
    float e = (lane < 12) ? expf(logit - mx) : 0.f;
    float ssum = e;
    #pragma unroll
    for (int s = 16; s > 0; s >>= 1) ssum += __shfl_xor_sync(0xffffffffu, ssum, s);
    const float wgt = e / ssum;

    uint32_t pA = 0, pB = 0;
    float w00 = 0.f, w01 = 0.f, w10 = 0.f, w11 = 0.f;
    if (lane < 12) {
        const float x0f = floorf(px), y0f = floorf(py);
        const float fx = px - x0f, fy = py - y0f;
        const int x0 = (int)x0f, y0 = (int)y0f;
        const int x1 = x0 + 1, y1 = y0 + 1;
        const bool vx0 = (unsigned)x0 < (unsigned)W, vx1 = (unsigned)x1 < (unsigned)W;
        const bool vy0 = (unsigned)y0 < (unsigned)W, vy1 = (unsigned)y1 < (unsigned)W;
        const int x0c = min(max(x0, 0), W - 1), x1c = min(max(x1, 0), W - 1);
        const int y0c = min(max(y0, 0), W - 1), y1c = min(max(y1, 0), W - 1);
        const uint32_t i00 = start + y0c * W + x0c, i01 = start + y0c * W + x1c;
        const uint32_t i10 = start + y1c * W + x0c, i11 = start + y1c * W + x1c;
        pA = i00 | (i01 << 16);
        pB = i10 | (i11 << 16);
        w00 = wgt * (1.f - fx) * (1.f - fy) * (float)(vx0 && vy0);
        w01 = wgt * fx * (1.f - fy) * (float)(vx1 && vy0);
        w10 = wgt * (1.f - fx) * fy * (float)(vx0 && vy1);
        w11 = wgt * fx * fy * (float)(vx1 && vy1);
    }

    const __half* vb = val + (size_t)b * LV * DMODEL + lane * 8;
    float acc[8];
    #pragma unroll
    for (int k = 0; k < 8; k++) acc[k] = 0.f;

    #pragma unroll
    for (int j = 0; j < 12; j++) {
        const uint32_t qA = __shfl_sync(0xffffffffu, pA, j);
        const uint32_t qB = __shfl_sync(0xffffffffu, pB, j);
        const float q00 = __shfl_sync(0xffffffffu, w00, j);
        const float q01 = __shfl_sync(0xffffffffu, w01, j);
        const float q10 = __shfl_sync(0xffffffffu, w10, j);
        const float q11 = __shfl_sync(0xffffffffu, w11, j);
        const int a00 = qA & 0xffff, a01 = qA >> 16;
        const int a10 = qB & 0xffff, a11 = qB >> 16;

        const uint4 u0 = *reinterpret_cast<const uint4*>(vb + (size_t)a00 * DMODEL);
        const uint4 u1 = *reinterpret_cast<const uint4*>(vb + (size_t)a01 * DMODEL);
        const uint4 u2 = *reinterpret_cast<const uint4*>(vb + (size_t)a10 * DMODEL);
        const uint4 u3 = *reinterpret_cast<const uint4*>(vb + (size_t)a11 * DMODEL);

        const __half2* h0 = reinterpret_cast<const __half2*>(&u0);
        const __half2* h1 = reinterpret_cast<const __half2*>(&u1);
        const __half2* h2 = reinterpret_cast<const __half2*>(&u2);
        const __half2* h3 = reinterpret_cast<const __half2*>(&u3);
        #pragma unroll
        for (int k = 0; k < 4; k++) {
            float2 f0 = __half22float2(h0[k]);
            float2 f1 = __half22float2(h1[k]);
            float2 f2 = __half22float2(h2[k]);
            float2 f3 = __half22float2(h3[k]);
            acc[2 * k + 0] += q00 * f0.x + q01 * f1.x + q10 * f2.x + q11 * f3.x;
            acc[2 * k + 1] += q00 * f0.y + q01 * f1.y + q10 * f2.y + q11 * f3.y;
        }
    }

    __half2 o[4];
    #pragma unroll
    for (int k = 0; k < 4; k++) o[k] = __floats2half2_rn(acc[2 * k], acc[2 * k + 1]);
    *reinterpret_cast<uint4*>(qv + ((size_t)h * MT_PAD + bq) * DMODEL + lane * 8) =
        *reinterpret_cast<uint4*>(o);
}

// ============================================================================
// proj: per-head projection, 64-row tiles.  grid (76, 8); 4 CTAs/SM.
// C[bq][h*32+c] = qv16[h][bq][:] @ Wv[:, h*32+c] + bv.
// 8 warps as 4(m) x 2(n): warp tile 16 rows x 16 cols.
// ============================================================================
__global__ __launch_bounds__(256, 4)
void proj_kernel(const __half* __restrict__ qv, const float* __restrict__ Wv,
                 const float* __restrict__ bv, __half* __restrict__ tmp) {
    extern __shared__ __half sh[];
    __half* As = sh;                      // [64][264]
    __half* Ws = sh + 64 * PJ_ASTR;       // [256][40]
    const uint32_t asb = smem_u32(As), wsb = smem_u32(Ws);
    const int tid = threadIdx.x, warp = tid >> 5, lane = tid & 31;
    const int wm = warp >> 1, wn = warp & 1;
    const int h = blockIdx.y;
    const int m0 = blockIdx.x * 64;

    // load A tile: 64 rows x 256 halves; each thread 64 halves (8 uint4)
    {
        const int row = tid >> 2, cb = (tid & 3) * 64;
        const __half* ap = qv + ((size_t)h * MT_PAD + m0 + row) * DMODEL + cb;
        #pragma unroll
        for (int i = 0; i < 8; i++)
            *reinterpret_cast<uint4*>(&As[row * PJ_ASTR + cb + 8 * i]) =
                *reinterpret_cast<const uint4*>(ap + 8 * i);
    }
    // load W slice [256][32] at h*32, cvt to fp16
    {
        const float* wp = Wv + (size_t)tid * 256 + h * 32;
        #pragma unroll
        for (int i = 0; i < 8; i++) {
            float4 v = *reinterpret_cast<const float4*>(wp + 4 * i);
            uint2 u = make_uint2(packh2(v.x, v.y), packh2(v.z, v.w));
            *reinterpret_cast<uint2*>(&Ws[tid * PJ_WSTR + 4 * i]) = u;
        }
    }
    __syncthreads();

    const uint32_t lrow = (uint32_t)(lane & 15);
    const uint32_t kadd = (uint32_t)(lane >> 4) * 8;

    float acc[2][4];
    #pragma unroll
    for (int i = 0; i < 2; i++)
        #pragma unroll
        for (int j = 0; j < 4; j++) acc[i][j] = 0.f;

    #pragma unroll
    for (int k16 = 0; k16 < 16; k16++) {
        uint32_t af[4], bf[2][2];
        ldsm_x4(af, asb + ((wm * 16 + lrow) * PJ_ASTR + k16 * 16 + kadd) * 2);
        {
            uint32_t r[4];
            ldsm_x4_t(r, wsb + ((k16 * 16 + lrow) * PJ_WSTR + wn * 16 + kadd) * 2);
            bf[0][0] = r[0]; bf[0][1] = r[1];
            bf[1][0] = r[2]; bf[1][1] = r[3];
        }
        #pragma unroll
        for (int ni = 0; ni < 2; ni++)
            mma16(acc[ni], af, bf[ni]);
    }

    const int g = lane >> 2, tg = lane & 3;
    const int r0 = m0 + wm * 16 + g, r1 = r0 + 8;
    #pragma unroll
    for (int ni = 0; ni < 2; ni++) {
        const int col = h * 32 + wn * 16 + ni * 8 + 2 * tg;
        const float b0 = bv[col], b1 = bv[col + 1];
        if (r0 < BQ)
            *reinterpret_cast<__half2*>(&tmp[(size_t)r0 * 256 + col]) =
                __floats2half2_rn(acc[ni][0] + b0, acc[ni][1] + b1);
        if (r1 < BQ)
            *reinterpret_cast<__half2*>(&tmp[(size_t)r1 * 256 + col]) =
                __floats2half2_rn(acc[ni][2] + b0, acc[ni][3] + b1);
    }
}

// ============================================================================
// gemm2 (triple-buffered, fp16 A / fp16 W / fp32 C, NTILE=64)
// ============================================================================
__global__ void __launch_bounds__(256, 2)
gemm2_kernel(const __half* __restrict__ A, const __half* __restrict__ W16,
             const float* __restrict__ bias, float* __restrict__ C, int Mstore) {
    constexpr int NTILE = 64, WN = 32, NI = 4, NQ = 2;
    constexpr int BSTRv = NTILE + 8;
    constexpr int STAGE = A_HALVES + 32 * BSTRv;

    extern __shared__ __half sh[];
    const uint32_t sb = smem_u32(sh);
    const int tid = threadIdx.x, warp = tid >> 5, lane = tid & 31;
    const int wm = warp >> 1, wn = warp & 1;
    const int g = lane >> 2, tg = lane & 3;
    const int m0 = blockIdx.x * 128;
    const int n0 = blockIdx.y * NTILE;

    const int arow = tid >> 1, ac0 = (tid & 1) * 16;
    const int brow = tid >> 3, bc0 = (tid & 7) * 8;

    float acc[2][NI][4];
    #pragma unroll
    for (int i = 0; i < 2; i++)
        #pragma unroll
        for (int j = 0; j < NI; j++)
            #pragma unroll
            for (int k = 0; k < 4; k++) acc[i][j][k] = 0.f;

    {
        const __half* ap = A + (size_t)(m0 + arow) * 256 + ac0;
        #pragma unroll
        for (int i = 0; i < 2; i++)
            *reinterpret_cast<uint4*>(&sh[arow * ASTR + ac0 + 8 * i]) =
                *reinterpret_cast<const uint4*>(ap + 8 * i);
        const __half* wp = W16 + (size_t)brow * 256 + n0 + bc0;
        *reinterpret_cast<uint4*>(&sh[A_HALVES + brow * BSTRv + bc0]) =
            *reinterpret_cast<const uint4*>(wp);
    }
    uint4 rah[2]; uint4 rb;
    {
        const __half* ap = A + (size_t)(m0 + arow) * 256 + BK + ac0;
        #pragma unroll
        for (int i = 0; i < 2; i++)
            rah[i] = *reinterpret_cast<const uint4*>(ap + 8 * i);
        rb = *reinterpret_cast<const uint4*>(W16 + (size_t)(BK + brow) * 256 + n0 + bc0);
    }
    __syncthreads();

    const uint32_t a_lrow = (uint32_t)(lane & 15);
    const uint32_t a_kadd = (uint32_t)(lane >> 4) * 8;

    #pragma unroll
    for (int c = 0; c < 8; c++) {
        if (c < 7) {
            __half* dst = &sh[((c + 1) % 3) * STAGE];
            #pragma unroll
            for (int i = 0; i < 2; i++)
                *reinterpret_cast<uint4*>(&dst[arow * ASTR + ac0 + 8 * i]) = rah[i];
            *reinterpret_cast<uint4*>(&dst[A_HALVES + brow * BSTRv + bc0]) = rb;
        }
        if (c < 6) {
            const int kc = (c + 2) * BK;
            const __half* ap = A + (size_t)(m0 + arow) * 256 + kc + ac0;
            #pragma unroll
            for (int i = 0; i < 2; i++)
                rah[i] = *reinterpret_cast<const uint4*>(ap + 8 * i);
            rb = *reinterpret_cast<const uint4*>(W16 + (size_t)(kc + brow) * 256 + n0 + bc0);
        }

        const uint32_t aB = sb + ((c % 3) * STAGE) * 2;
        const uint32_t bB = aB + A_HALVES * 2;
        #pragma unroll
        for (int k16 = 0; k16 < 2; k16++) {
            uint32_t af[2][4], bf[NI][2];
            #pragma unroll
            for (int mi = 0; mi < 2; mi++)
                ldsm_x4(af[mi], aB + ((wm * 32 + mi * 16 + a_lrow) * ASTR
                                      + k16 * 16 + a_kadd) * 2);
            #pragma unroll
            for (int nq = 0; nq < NQ; nq++) {
                uint32_t r[4];
                ldsm_x4_t(r, bB + ((k16 * 16 + a_lrow) * BSTRv
                                   + wn * WN + nq * 16 + a_kadd) * 2);
                bf[2 * nq][0] = r[0]; bf[2 * nq][1] = r[1];
                bf[2 * nq + 1][0] = r[2]; bf[2 * nq + 1][1] = r[3];
            }
            #pragma unroll
            for (int mi = 0; mi < 2; mi++)
                #pragma unroll
                for (int ni = 0; ni < NI; ni++)
                    mma16(acc[mi][ni], af[mi], bf[ni]);
        }
        if (c < 7) __syncthreads();
    }

    #pragma unroll
    for (int mi = 0; mi < 2; mi++) {
        const int r0 = m0 + wm * 32 + mi * 16 + g;
        const int r1 = r0 + 8;
        #pragma unroll
        for (int ni = 0; ni < NI; ni++) {
            const int cc = n0 + wn * WN + ni * 8 + 2 * tg;
            const float b0 = bias[cc], b1 = bias[cc + 1];
            if (r0 < Mstore)
                *reinterpret_cast<float2*>(&C[(size_t)r0 * 256 + cc]) =
                    make_float2(acc[mi][ni][0] + b0, acc[mi][ni][1] + b1);
            if (r1 < Mstore)
                *reinterpret_cast<float2*>(&C[(size_t)r1 * 256 + cc]) =
                    make_float2(acc[mi][ni][2] + b0, acc[mi][ni][3] + b1);
        }
    }
}

// ============================================================================
extern "C" void kernel_launch(void* const* d_in, const int* in_sizes, int n_in,
                              void* d_out, int out_size) {
    const float* query = (const float*)d_in[0];
    const float* rp    = (const float*)d_in[1];
    const float* value = (const float*)d_in[2];
    const float* Wv    = (const float*)d_in[3];
    const float* bv    = (const float*)d_in[4];
    const float* Woff  = (const float*)d_in[5];
    const float* boff  = (const float*)d_in[6];
    const float* Wattn = (const float*)d_in[7];
    const float* battn = (const float*)d_in[8];
    const float* Wout  = (const float*)d_in[9];
    const float* bout  = (const float*)d_in[10];
    float* out = (float*)d_out;

    __half *pval16, *pqv16, *ptmp16, *pwo16;
    float *poff, *pattn;
    cudaGetSymbolAddress((void**)&pval16, g_val16);
    cudaGetSymbolAddress((void**)&pqv16,  g_qv16);
    cudaGetSymbolAddress((void**)&ptmp16, g_tmp16);
    cudaGetSymbolAddress((void**)&pwo16,  g_wo16);
    cudaGetSymbolAddress((void**)&poff,   g_off);
    cudaGetSymbolAddress((void**)&pattn,  g_attn);

    static bool attr_done = false;
    if (!attr_done) {
        cudaFuncSetAttribute(proj_kernel, cudaFuncAttributeMaxDynamicSharedMemorySize, SMEM_PJ);
        cudaFuncSetAttribute(gemm2_kernel, cudaFuncAttributeMaxDynamicSharedMemorySize, SMEM_G2);
        attr_done = true;
    }

    // 1) value -> fp16 (+ Wout -> fp16), DRAM-bound
    cvt_all<<<(NTOT / 4 + 255) / 256, 256>>>(value, pval16, Wout, pwo16);
    // 2) offsets + attn logits (exact fp32)
    fgemm_qfused<<<dim3(9, BQ / 32), 256>>>(query, Woff, boff, Wattn, battn, poff, pattn);
    // 3) softmax + bilinear gather + point-reduce in RAW value space (L2-bound)
    sample_reduce<<<BQ, 256>>>(poff, pattn, rp, pval16, pqv16);
    // 4) per-head 256->32 projection (64-row tiles, 608 CTAs)
    proj_kernel<<<dim3(MT_PAD / 64, NHEADS), 256, SMEM_PJ>>>(pqv16, Wv, bv, ptmp16);
    // 5) out = tmp @ Wout + bout
    gemm2_kernel<<<dim3(MT_PAD / 128, 4), 256, SMEM_G2>>>(ptmp16, pwo16, bout, out, BQ);
}

// round 14
// speedup vs baseline: 1.1481x; 1.1481x over previous
#include <cuda_runtime.h>
#include <cuda_fp16.h>
#include <cstdint>
#include <type_traits>

// ---------------- problem constants ----------------
#define B_      16
#define Q_      300
#define DMODEL  256
#define NHEADS  8
#define HD      32
#define LV      8400          // 80*80 + 40*40 + 20*20
#define BQ      (B_*Q_)       // 4800
#define MV      (B_*LV)       // 134400 value rows
#define MT_PAD  4864          // 38*128

// ---------------- scratch (device globals; zero-initialized) ----------------
__device__ __half g_val16[MV * DMODEL];               // raw value, fp16
__device__ __half g_qv16[NHEADS * MT_PAD * DMODEL];   // reduced sample vecs [h][bq][256]
__device__ __half g_tmp16[MT_PAD * DMODEL];           // projected heads; pad rows stay 0
__device__ __half g_wo16[DMODEL * DMODEL];            // Wout fp16
__device__ __half g_wv16[DMODEL * DMODEL];            // Wv fp16
__device__ float  g_off[BQ * 192];
__device__ float  g_attn[BQ * 96];

// ---------------- helpers ----------------
__device__ __forceinline__ uint32_t smem_u32(const void* p) {
    uint32_t a;
    asm("{ .reg .u64 t; cvta.to.shared.u64 t, %1; cvt.u32.u64 %0, t; }" : "=r"(a) : "l"(p));
    return a;
}
__device__ __forceinline__ void ldsm_x4(uint32_t* r, uint32_t addr) {
    asm volatile("ldmatrix.sync.aligned.m8n8.x4.shared.b16 {%0,%1,%2,%3}, [%4];"
                 : "=r"(r[0]), "=r"(r[1]), "=r"(r[2]), "=r"(r[3]) : "r"(addr));
}
__device__ __forceinline__ void ldsm_x4_t(uint32_t* r, uint32_t addr) {
    asm volatile("ldmatrix.sync.aligned.m8n8.x4.trans.shared.b16 {%0,%1,%2,%3}, [%4];"
                 : "=r"(r[0]), "=r"(r[1]), "=r"(r[2]), "=r"(r[3]) : "r"(addr));
}
__device__ __forceinline__ void mma16(float* c, const uint32_t* a, const uint32_t* b) {
    asm volatile(
        "mma.sync.aligned.m16n8k16.row.col.f32.f16.f16.f32 "
        "{%0,%1,%2,%3}, {%4,%5,%6,%7}, {%8,%9}, {%0,%1,%2,%3};\n"
        : "+f"(c[0]), "+f"(c[1]), "+f"(c[2]), "+f"(c[3])
        : "r"(a[0]), "r"(a[1]), "r"(a[2]), "r"(a[3]), "r"(b[0]), "r"(b[1]));
}
__device__ __forceinline__ uint32_t packh2(float x, float y) {
    __half2 h = __floats2half2_rn(x, y);
    return *reinterpret_cast<uint32_t*>(&h);
}

// ---------------- geometry ----------------
#define BK       32
#define ASTR     40
#define A_HALVES (128 * ASTR)
#define STAGE_G2 (A_HALVES + 32 * 72)
#define SMEM_G2  (3 * STAGE_G2 * 2)         // 44544 B
#define STAGE_PJ (A_HALVES + 32 * 40)
#define SMEM_PJ  (3 * STAGE_PJ * 2)         // 38400 B

#define WSZ  (DMODEL * DMODEL)             // 65536
#define NVAL (MV * DMODEL)                 // 34,406,400
#define NTOT (NVAL + 2 * WSZ)

// ============================================================================
// fp32 -> fp16: value + Wout + Wv in one launch
// ============================================================================
__global__ void cvt_all(const float* __restrict__ val, __half* __restrict__ dval,
                        const float* __restrict__ wo, __half* __restrict__ dwo,
                        const float* __restrict__ wv, __half* __restrict__ dwv) {
    long i = ((long)blockIdx.x * blockDim.x + threadIdx.x) * 4;
    if (i >= NTOT) return;
    const float* s; __half* d; long j;
    if (i < NVAL)            { s = val; d = dval; j = i; }
    else if (i < NVAL + WSZ) { s = wo;  d = dwo;  j = i - NVAL; }
    else                     { s = wv;  d = dwv;  j = i - NVAL - WSZ; }
    float4 v = *reinterpret_cast<const float4*>(s + j);
    uint2 u = make_uint2(packh2(v.x, v.y), packh2(v.z, v.w));
    *reinterpret_cast<uint2*>(d + j) = u;
}

// ============================================================================
// Fused exact fp32 GEMM for offsets + attn logits. Tile 32x32, BK=64.
// grid (9, 150). bx 0..5 -> Woff/g_off, 6..8 -> Wattn/g_attn.
// ============================================================================
__global__ __launch_bounds__(256, 6)
void fgemm_qfused(const float* __restrict__ A,
                  const float* __restrict__ Woff, const float* __restrict__ boff,
                  const float* __restrict__ Wattn, const float* __restrict__ battn,
                  float* __restrict__ Coff, float* __restrict__ Cattn) {
    __shared__ float As[32 * 68];
    __shared__ float Bs[64 * 36];
    const int tid = threadIdx.x;
    const int bx = blockIdx.x;
    const int m0 = blockIdx.y * 32;

    const float* Bm; const float* bias; float* C; int N; int n0;
    if (bx < 6) { Bm = Woff;  bias = boff;  C = Coff;  N = 192; n0 = bx * 32; }
    else        { Bm = Wattn; bias = battn; C = Cattn; N = 96;  n0 = (bx - 6) * 32; }

    const int ty = tid >> 4, tx = tid & 15;
    const int arow = tid >> 3, acol = (tid & 7) * 4;

    float acc[2][2] = {};
    for (int kc = 0; kc < 256; kc += 64) {
        #pragma unroll
        for (int i = 0; i < 2; i++)
            *reinterpret_cast<float4*>(&As[arow * 68 + acol + 32 * i]) =
                *reinterpret_cast<const float4*>(A + (size_t)(m0 + arow) * 256 + kc + acol + 32 * i);
        #pragma unroll
        for (int i = 0; i < 2; i++)
            *reinterpret_cast<float4*>(&Bs[(arow + 32 * i) * 36 + acol]) =
                *reinterpret_cast<const float4*>(Bm + (size_t)(kc + arow + 32 * i) * N + n0 + acol);
        __syncthreads();
        #pragma unroll
        for (int kk = 0; kk < 64; kk++) {
            const float a0 = As[(ty * 2 + 0) * 68 + kk];
            const float a1 = As[(ty * 2 + 1) * 68 + kk];
            const float2 bv = *reinterpret_cast<const float2*>(&Bs[kk * 36 + tx * 2]);
            acc[0][0] += a0 * bv.x;  acc[0][1] += a0 * bv.y;
            acc[1][0] += a1 * bv.x;  acc[1][1] += a1 * bv.y;
        }
        __syncthreads();
    }
    const float b0 = bias[n0 + tx * 2], b1 = bias[n0 + tx * 2 + 1];
    #pragma unroll
    for (int i = 0; i < 2; i++) {
        float2 v = make_float2(acc[i][0] + b0, acc[i][1] + b1);
        *reinterpret_cast<float2*>(&C[(size_t)(m0 + ty * 2 + i) * N + n0 + tx * 2]) = v;
    }
}

// ============================================================================
// sample_reduce: one warp per (bq, h). Lanes 0-11 own a (level,point):
// softmax + clamped corner indices + validity-folded weights. All 32 lanes
// gather RAW 256-dim fp16 value rows (8 dims/lane) and weighted-accumulate
// over 12 points x 4 corners -> g_qv16[h][bq][256].
// ============================================================================
__global__ __launch_bounds__(256)
void sample_reduce(const float* __restrict__ off, const float* __restrict__ attn,
                   const float* __restrict__ rp, const __half* __restrict__ val,
                   __half* __restrict__ qv) {
    const int bq   = blockIdx.x;
    const int h    = threadIdx.x >> 5;
    const int lane = threadIdx.x & 31;
    const int b    = bq / Q_;

    const float refx = rp[bq * 4 + 0];
    const float refy = rp[bq * 4 + 1];

    float logit = -1e30f, px = 0.f, py = 0.f;
    int W = 1, start = 0;
    if (lane < 12) {
        logit = attn[bq * 96 + h * 12 + lane];
        const float ox = off[bq * 192 + h * 24 + lane * 2 + 0];
        const float oy = off[bq * 192 + h * 24 + lane * 2 + 1];
        const int lvl = lane >> 2;
        W     = (lvl == 0) ? 80 : ((lvl == 1) ? 40 : 20);
        start = (lvl == 0) ? 0 : ((lvl == 1) ? 6400 : 8000);
        const float Wf = (float)W;
        const float ptsx = fminf(fmaxf(refx + ox, 0.f), 1.f);
        const float ptsy = fminf(fmaxf(refy + oy, 0.f), 1.f);
        px = ptsx * Wf - 0.5f;
        py = ptsy * Wf - 0.5f;
    }
    float mx = logit;
    #pragma unroll
    for (int s = 16; s > 0; s >>= 1) mx = fmaxf(mx, __shfl_xor_sync(0xffffffffu, mx, s));
    float e = (lane < 12) ? expf(logit - mx) : 0.f;
    float ssum = e;
    #pragma unroll
    for (int s = 16; s > 0; s >>= 1) ssum += __shfl_xor_sync(0xffffffffu, ssum, s);
    const float wgt = e / ssum;

    uint32_t pA = 0, pB = 0;
    float w00 = 0.f, w01 = 0.f, w10 = 0.f, w11 = 0.f;
    if (lane < 12) {
        const float x0f = floorf(px), y0f = floorf(py);
        const float fx = px - x0f, fy = py - y0f;
        const int x0 = (int)x0f, y0 = (int)y0f;
        const int x1 = x0 + 1, y1 = y0 + 1;
        const bool vx0 = (unsigned)x0 < (unsigned)W, vx1 = (unsigned)x1 < (unsigned)W;
        const bool vy0 = (unsigned)y0 < (unsigned)W, vy1 = (unsigned)y1 < (unsigned)W;
        const int x0c = min(max(x0, 0), W - 1), x1c = min(max(x1, 0), W - 1);
        const int y0c = min(max(y0, 0), W - 1), y1c = min(max(y1, 0), W - 1);
        const uint32_t i00 = start + y0c * W + x0c, i01 = start + y0c * W + x1c;
        const uint32_t i10 = start + y1c * W + x0c, i11 = start + y1c * W + x1c;
        pA = i00 | (i01 << 16);
        pB = i10 | (i11 << 16);
        w00 = wgt * (1.f - fx) * (1.f - fy) * (float)(vx0 && vy0);
        w01 = wgt * fx * (1.f - fy) * (float)(vx1 && vy0);
        w10 = wgt * (1.f - fx) * fy * (float)(vx0 && vy1);
        w11 = wgt * fx * fy * (float)(vx1 && vy1);
    }

    const __half* vb = val + (size_t)b * LV * DMODEL + lane * 8;
    float acc[8];
    #pragma unroll
    for (int k = 0; k < 8; k++) acc[k] = 0.f;

    #pragma unroll
    for (int j = 0; j < 12; j++) {
        const uint32_t qA = __shfl_sync(0xffffffffu, pA, j);
        const uint32_t qB = __shfl_sync(0xffffffffu, pB, j);
        const float q00 = __shfl_sync(0xffffffffu, w00, j);
        const float q01 = __shfl_sync(0xffffffffu, w01, j);
        const float q10 = __shfl_sync(0xffffffffu, w10, j);
        const float q11 = __shfl_sync(0xffffffffu, w11, j);
        const int a00 = qA & 0xffff, a01 = qA >> 16;
        const int a10 = qB & 0xffff, a11 = qB >> 16;

        const uint4 u0 = *reinterpret_cast<const uint4*>(vb + (size_t)a00 * DMODEL);
        const uint4 u1 = *reinterpret_cast<const uint4*>(vb + (size_t)a01 * DMODEL);
        const uint4 u2 = *reinterpret_cast<const uint4*>(vb + (size_t)a10 * DMODEL);
        const uint4 u3 = *reinterpret_cast<const uint4*>(vb + (size_t)a11 * DMODEL);

        const __half2* h0 = reinterpret_cast<const __half2*>(&u0);
        const __half2* h1 = reinterpret_cast<const __half2*>(&u1);
        const __half2* h2 = reinterpret_cast<const __half2*>(&u2);
        const __half2* h3 = reinterpret_cast<const __half2*>(&u3);
        #pragma unroll
        for (int k = 0; k < 4; k++) {
            float2 f0 = __half22float2(h0[k]);
            float2 f1 = __half22float2(h1[k]);
            float2 f2 = __half22float2(h2[k]);
            float2 f3 = __half22float2(h3[k]);
            acc[2 * k + 0] += q00 * f0.x + q01 * f1.x + q10 * f2.x + q11 * f3.x;
            acc[2 * k + 1] += q00 * f0.y + q01 * f1.y + q10 * f2.y + q11 * f3.y;
        }
    }

    __half2 o[4];
    #pragma unroll
    for (int k = 0; k < 4; k++) o[k] = __floats2half2_rn(acc[2 * k], acc[2 * k + 1]);
    *reinterpret_cast<uint4*>(qv + ((size_t)h * MT_PAD + bq) * DMODEL + lane * 8) =
        *reinterpret_cast<uint4*>(o);
}

// ============================================================================
// proj: per-head projection, triple-buffered GEMM (NTILE=32).
// grid (38, 8): m-tile x head.  tmp[bq][h*32+c] = qv[h][bq][:] @ Wv16[:,h*32+c] + bv.
// Same pipeline as gemm2: STS chunk c+1 (loaded a full iter ago), LDG c+2,
// compute c — DRAM latency on qv reads fully hidden.
// ============================================================================
__global__ void __launch_bounds__(256, 2)
proj_kernel(const __half* __restrict__ qv, const __half* __restrict__ Wv16,
            const float* __restrict__ bv, __half* __restrict__ tmp) {
    constexpr int NTILE = 32, WN = 16, NI = 2;
    constexpr int BSTRv = NTILE + 8;               // 40
    constexpr int STAGE = A_HALVES + 32 * BSTRv;

    extern __shared__ __half sh[];
    const uint32_t sb = smem_u32(sh);
    const int tid = threadIdx.x, warp = tid >> 5, lane = tid & 31;
    const int wm = warp >> 1, wn = warp & 1;
    const int g = lane >> 2, tg = lane & 3;
    const int h = blockIdx.y;
    const int m0 = blockIdx.x * 128;

    const __half* A = qv + (size_t)h * MT_PAD * DMODEL;
    const __half* Wp = Wv16 + h * 32;              // column slice; row stride 256

    const int arow = tid >> 1, ac0 = (tid & 1) * 16;
    const int brow = tid >> 3, bc0 = (tid & 7) * 4;

    float acc[2][NI][4];
    #pragma unroll
    for (int i = 0; i < 2; i++)
        #pragma unroll
        for (int j = 0; j < NI; j++)
            #pragma unroll
            for (int k = 0; k < 4; k++) acc[i][j][k] = 0.f;

    // prologue: chunk 0 -> buf0; chunk 1 -> regs
    {
        const __half* ap = A + (size_t)(m0 + arow) * 256 + ac0;
        #pragma unroll
        for (int i = 0; i < 2; i++)
            *reinterpret_cast<uint4*>(&sh[arow * ASTR + ac0 + 8 * i]) =
                *reinterpret_cast<const uint4*>(ap + 8 * i);
        *reinterpret_cast<uint2*>(&sh[A_HALVES + brow * BSTRv + bc0]) =
            *reinterpret_cast<const uint2*>(Wp + (size_t)brow * 256 + bc0);
    }
    uint4 rah[2]; uint2 rb;
    {
        const __half* ap = A + (size_t)(m0 + arow) * 256 + BK + ac0;
        #pragma unroll
        for (int i = 0; i < 2; i++)
            rah[i] = *reinterpret_cast<const uint4*>(ap + 8 * i);
        rb = *reinterpret_cast<const uint2*>(Wp + (size_t)(BK + brow) * 256 + bc0);
    }
    __syncthreads();

    const uint32_t a_lrow = (uint32_t)(lane & 15);
    const uint32_t a_kadd = (uint32_t)(lane >> 4) * 8;

    #pragma unroll
    for (int c = 0; c < 8; c++) {
        if (c < 7) {
            __half* dst = &sh[((c + 1) % 3) * STAGE];
            #pragma unroll
            for (int i = 0; i < 2; i++)
                *reinterpret_cast<uint4*>(&dst[arow * ASTR + ac0 + 8 * i]) = rah[i];
            *reinterpret_cast<uint2*>(&dst[A_HALVES + brow * BSTRv + bc0]) = rb;
        }
        if (c < 6) {
            const int kc = (c + 2) * BK;
            const __half* ap = A + (size_t)(m0 + arow) * 256 + kc + ac0;
            #pragma unroll
            for (int i = 0; i < 2; i++)
                rah[i] = *reinterpret_cast<const uint4*>(ap + 8 * i);
            rb = *reinterpret_cast<const uint2*>(Wp + (size_t)(kc + brow) * 256 + bc0);
        }

        const uint32_t aB = sb + ((c % 3) * STAGE) * 2;
        const uint32_t bB = aB + A_HALVES * 2;
        #pragma unroll
        for (int k16 = 0; k16 < 2; k16++) {
            uint32_t af[2][4], bf[NI][2];
            #pragma unroll
            for (int mi = 0; mi < 2; mi++)
                ldsm_x4(af[mi], aB + ((wm * 32 + mi * 16 + a_lrow) * ASTR
                                      + k16 * 16 + a_kadd) * 2);
            {
                uint32_t r[4];
                ldsm_x4_t(r, bB + ((k16 * 16 + a_lrow) * BSTRv
                                   + wn * WN + a_kadd) * 2);
                bf[0][0] = r[0]; bf[0][1] = r[1];
                bf[1][0] = r[2]; bf[1][1] = r[3];
            }
            #pragma unroll
            for (int mi = 0; mi < 2; mi++)
                #pragma unroll
                for (int ni = 0; ni < NI; ni++)
                    mma16(acc[mi][ni], af[mi], bf[ni]);
        }
        if (c < 7) __syncthreads();
    }

    // epilogue: fp16 half2 stores into column slice h*32 + [0,32)
    #pragma unroll
    for (int mi = 0; mi < 2; mi++) {
        const int r0 = m0 + wm * 32 + mi * 16 + g;
        const int r1 = r0 + 8;
        #pragma unroll
        for (int ni = 0; ni < NI; ni++) {
            const int col = h * 32 + wn * WN + ni * 8 + 2 * tg;
            const float b0 = bv[col], b1 = bv[col + 1];
            if (r0 < BQ)
                *reinterpret_cast<__half2*>(&tmp[(size_t)r0 * 256 + col]) =
                    __floats2half2_rn(acc[mi][ni][0] + b0, acc[mi][ni][1] + b1);
            if (r1 < BQ)
                *reinterpret_cast<__half2*>(&tmp[(size_t)r1 * 256 + col]) =
                    __floats2half2_rn(acc[mi][ni][2] + b0, acc[mi][ni][3] + b1);
        }
    }
}

// ============================================================================
// gemm2 (triple-buffered, fp16 A / fp16 W / fp32 C, NTILE=64)
// ============================================================================
__global__ void __launch_bounds__(256, 2)
gemm2_kernel(const __half* __restrict__ A, const __half* __restrict__ W16,
             const float* __restrict__ bias, float* __restrict__ C, int Mstore) {
    constexpr int NTILE = 64, WN = 32, NI = 4, NQ = 2;
    constexpr int BSTRv = NTILE + 8;
    constexpr int STAGE = A_HALVES + 32 * BSTRv;

    extern __shared__ __half sh[];
    const uint32_t sb = smem_u32(sh);
    const int tid = threadIdx.x, warp = tid >> 5, lane = tid & 31;
    const int wm = warp >> 1, wn = warp & 1;
    const int g = lane >> 2, tg = lane & 3;
    const int m0 = blockIdx.x * 128;
    const int n0 = blockIdx.y * NTILE;

    const int arow = tid >> 1, ac0 = (tid & 1) * 16;
    const int brow = tid >> 3, bc0 = (tid & 7) * 8;

    float acc[2][NI][4];
    #pragma unroll
    for (int i = 0; i < 2; i++)
        #pragma unroll
        for (int j = 0; j < NI; j++)
            #pragma unroll
            for (int k = 0; k < 4; k++) acc[i][j][k] = 0.f;

    {
        const __half* ap = A + (size_t)(m0 + arow) * 256 + ac0;
        #pragma unroll
        for (int i = 0; i < 2; i++)
            *reinterpret_cast<uint4*>(&sh[arow * ASTR + ac0 + 8 * i]) =
                *reinterpret_cast<const uint4*>(ap + 8 * i);
        const __half* wp = W16 + (size_t)brow * 256 + n0 + bc0;
        *reinterpret_cast<uint4*>(&sh[A_HALVES + brow * BSTRv + bc0]) =
            *reinterpret_cast<const uint4*>(wp);
    }
    uint4 rah[2]; uint4 rb;
    {
        const __half* ap = A + (size_t)(m0 + arow) * 256 + BK + ac0;
        #pragma unroll
        for (int i = 0; i < 2; i++)
            rah[i] = *reinterpret_cast<const uint4*>(ap + 8 * i);
        rb = *reinterpret_cast<const uint4*>(W16 + (size_t)(BK + brow) * 256 + n0 + bc0);
    }
    __syncthreads();

    const uint32_t a_lrow = (uint32_t)(lane & 15);
    const uint32_t a_kadd = (uint32_t)(lane >> 4) * 8;

    #pragma unroll
    for (int c = 0; c < 8; c++) {
        if (c < 7) {
            __half* dst = &sh[((c + 1) % 3) * STAGE];
            #pragma unroll
            for (int i = 0; i < 2; i++)
                *reinterpret_cast<uint4*>(&dst[arow * ASTR + ac0 + 8 * i]) = rah[i];
            *reinterpret_cast<uint4*>(&dst[A_HALVES + brow * BSTRv + bc0]) = rb;
        }
        if (c < 6) {
            const int kc = (c + 2) * BK;
            const __half* ap = A + (size_t)(m0 + arow) * 256 + kc + ac0;
            #pragma unroll
            for (int i = 0; i < 2; i++)
                rah[i] = *reinterpret_cast<const uint4*>(ap + 8 * i);
            rb = *reinterpret_cast<const uint4*>(W16 + (size_t)(kc + brow) * 256 + n0 + bc0);
        }

        const uint32_t aB = sb + ((c % 3) * STAGE) * 2;
        const uint32_t bB = aB + A_HALVES * 2;
        #pragma unroll
        for (int k16 = 0; k16 < 2; k16++) {
            uint32_t af[2][4], bf[NI][2];
            #pragma unroll
            for (int mi = 0; mi < 2; mi++)
                ldsm_x4(af[mi], aB + ((wm * 32 + mi * 16 + a_lrow) * ASTR
                                      + k16 * 16 + a_kadd) * 2);
            #pragma unroll
            for (int nq = 0; nq < NQ; nq++) {
                uint32_t r[4];
                ldsm_x4_t(r, bB + ((k16 * 16 + a_lrow) * BSTRv
                                   + wn * WN + nq * 16 + a_kadd) * 2);
                bf[2 * nq][0] = r[0]; bf[2 * nq][1] = r[1];
                bf[2 * nq + 1][0] = r[2]; bf[2 * nq + 1][1] = r[3];
            }
            #pragma unroll
            for (int mi = 0; mi < 2; mi++)
                #pragma unroll
                for (int ni = 0; ni < NI; ni++)
                    mma16(acc[mi][ni], af[mi], bf[ni]);
        }
        if (c < 7) __syncthreads();
    }

    #pragma unroll
    for (int mi = 0; mi < 2; mi++) {
        const int r0 = m0 + wm * 32 + mi * 16 + g;
        const int r1 = r0 + 8;
        #pragma unroll
        for (int ni = 0; ni < NI; ni++) {
            const int cc = n0 + wn * WN + ni * 8 + 2 * tg;
            const float b0 = bias[cc], b1 = bias[cc + 1];
            if (r0 < Mstore)
                *reinterpret_cast<float2*>(&C[(size_t)r0 * 256 + cc]) =
                    make_float2(acc[mi][ni][0] + b0, acc[mi][ni][1] + b1);
            if (r1 < Mstore)
                *reinterpret_cast<float2*>(&C[(size_t)r1 * 256 + cc]) =
                    make_float2(acc[mi][ni][2] + b0, acc[mi][ni][3] + b1);
        }
    }
}

// ============================================================================
extern "C" void kernel_launch(void* const* d_in, const int* in_sizes, int n_in,
                              void* d_out, int out_size) {
    const float* query = (const float*)d_in[0];
    const float* rp    = (const float*)d_in[1];
    const float* value = (const float*)d_in[2];
    const float* Wv    = (const float*)d_in[3];
    const float* bv    = (const float*)d_in[4];
    const float* Woff  = (const float*)d_in[5];
    const float* boff  = (const float*)d_in[6];
    const float* Wattn = (const float*)d_in[7];
    const float* battn = (const float*)d_in[8];
    const float* Wout  = (const float*)d_in[9];
    const float* bout  = (const float*)d_in[10];
    float* out = (float*)d_out;

    __half *pval16, *pqv16, *ptmp16, *pwo16, *pwv16;
    float *poff, *pattn;
    cudaGetSymbolAddress((void**)&pval16, g_val16);
    cudaGetSymbolAddress((void**)&pqv16,  g_qv16);
    cudaGetSymbolAddress((void**)&ptmp16, g_tmp16);
    cudaGetSymbolAddress((void**)&pwo16,  g_wo16);
    cudaGetSymbolAddress((void**)&pwv16,  g_wv16);
    cudaGetSymbolAddress((void**)&poff,   g_off);
    cudaGetSymbolAddress((void**)&pattn,  g_attn);

    static bool attr_done = false;
    if (!attr_done) {
        cudaFuncSetAttribute(proj_kernel, cudaFuncAttributeMaxDynamicSharedMemorySize, SMEM_PJ);
        cudaFuncSetAttribute(gemm2_kernel, cudaFuncAttributeMaxDynamicSharedMemorySize, SMEM_G2);
        attr_done = true;
    }

    // 1) value -> fp16 (+ Wout, Wv -> fp16), DRAM-bound
    cvt_all<<<(NTOT / 4 + 255) / 256, 256>>>(value, pval16, Wout, pwo16, Wv, pwv16);
    // 2) offsets + attn logits (exact fp32)
    fgemm_qfused<<<dim3(9, BQ / 32), 256>>>(query, Woff, boff, Wattn, battn, poff, pattn);
    // 3) softmax + bilinear gather + point-reduce in RAW value space (L2-bound)
    sample_reduce<<<BQ, 256>>>(poff, pattn, rp, pval16, pqv16);
    // 4) per-head 256->32 projection (triple-buffered, DRAM-latency tolerant)
    proj_kernel<<<dim3(MT_PAD / 128, NHEADS), 256, SMEM_PJ>>>(pqv16, pwv16, bv, ptmp16);
    // 5) out = tmp @ Wout + bout
    gemm2_kernel<<<dim3(MT_PAD / 128, 4), 256, SMEM_G2>>>(ptmp16, pwo16, bout, out, BQ);
}